// round 8
// baseline (speedup 1.0000x reference)
#include <cuda_runtime.h>
#include <cstdint>
#include <cstring>

#define SQ 512
#define BB 64
#define EE 128
#define HH 256
#define NG 1024   // 4*H

// ---------------- scratch (static device memory; no allocations) ----------------
__device__ float g_x [SQ*BB*EE];          // embedded inputs          16 MB
__device__ float g_xg[(size_t)SQ*BB*NG];  // forward input-gate proj  128 MB
__device__ float g_gb[BB*NG];             // backward first-step gates
__device__ float g_hf[BB*HH];             // final forward h
__device__ float g_hb[BB*HH];             // backward first-step h

typedef unsigned long long ull;

__device__ __forceinline__ void fma2(ull& d, ull a, ull b) {
    asm("fma.rn.f32x2 %0, %1, %2, %0;" : "+l"(d) : "l"(a), "l"(b));
}
__device__ __forceinline__ ull pk(float x, float y) {
    float2 f = make_float2(x, y); ull v; memcpy(&v, &f, 8); return v;
}
__device__ __forceinline__ float2 unpk(ull v) {
    float2 f; memcpy(&f, &v, 8); return f;
}
__device__ __forceinline__ float sigf(float x)  { return 1.f/(1.f+__expf(-x)); }
__device__ __forceinline__ float tanhf_(float x){ return 1.f - 2.f/(__expf(2.f*x)+1.f); }

// ---------------- kernel 1: embedding gather ----------------
__global__ void k_embed(const int* __restrict__ seq, const float* __restrict__ emb,
                        float* __restrict__ x)
{
    int row  = blockIdx.x * 4 + (threadIdx.x >> 5);
    int lane = threadIdx.x & 31;
    int idx  = seq[row];
    float4 v;
    if (idx == 0) v = make_float4(0.f, 0.f, 0.f, 0.f);
    else          v = ((const float4*)emb)[(size_t)idx * 32 + lane];
    ((float4*)x)[(size_t)row * 32 + lane] = v;
}

// ---------------- kernel 2: C[M,1024] = A[M,128] @ W[1024,128]^T + bias ----------------
__global__ void __launch_bounds__(256)
k_gemm(const float* __restrict__ A, const float* __restrict__ W,
       const float* __restrict__ bias, float* __restrict__ C)
{
    extern __shared__ float sm[];
    float* As = sm;             // [128][68]
    float* Bs = sm + 128*68;    // [128][68]

    const int tid = threadIdx.x;
    const int gm0 = blockIdx.y * 64;
    const int gn0 = blockIdx.x * 64;

#pragma unroll
    for (int i = 0; i < 8; ++i) {
        int e   = tid + i * 256;
        int row = e >> 5;
        int kq  = e & 31;
        float4 a = ((const float4*)A)[(size_t)(gm0 + row) * 32 + kq];
        As[(4*kq+0)*68 + row] = a.x;
        As[(4*kq+1)*68 + row] = a.y;
        As[(4*kq+2)*68 + row] = a.z;
        As[(4*kq+3)*68 + row] = a.w;
        float4 w = ((const float4*)W)[(size_t)(gn0 + row) * 32 + kq];
        Bs[(4*kq+0)*68 + row] = w.x;
        Bs[(4*kq+1)*68 + row] = w.y;
        Bs[(4*kq+2)*68 + row] = w.z;
        Bs[(4*kq+3)*68 + row] = w.w;
    }
    __syncthreads();

    const int tx = tid & 15, ty = tid >> 4;
    const int m0 = ty * 4, n0 = tx * 4;

    float b0 = bias[gn0+n0+0], b1 = bias[gn0+n0+1];
    float b2 = bias[gn0+n0+2], b3 = bias[gn0+n0+3];
    ull acc[4][2];
#pragma unroll
    for (int i = 0; i < 4; ++i) { acc[i][0] = pk(b0,b1); acc[i][1] = pk(b2,b3); }

#pragma unroll 4
    for (int k = 0; k < 128; ++k) {
        float4 a4 = *(const float4*)&As[k*68 + m0];
        ulonglong2 bb = *(const ulonglong2*)&Bs[k*68 + n0];
        ull ad;
        ad = pk(a4.x, a4.x); fma2(acc[0][0], ad, bb.x); fma2(acc[0][1], ad, bb.y);
        ad = pk(a4.y, a4.y); fma2(acc[1][0], ad, bb.x); fma2(acc[1][1], ad, bb.y);
        ad = pk(a4.z, a4.z); fma2(acc[2][0], ad, bb.x); fma2(acc[2][1], ad, bb.y);
        ad = pk(a4.w, a4.w); fma2(acc[3][0], ad, bb.x); fma2(acc[3][1], ad, bb.y);
    }

#pragma unroll
    for (int i = 0; i < 4; ++i) {
        float2 lo = unpk(acc[i][0]), hi = unpk(acc[i][1]);
        float4 o = make_float4(lo.x, lo.y, hi.x, hi.y);
        ((float4*)C)[(size_t)(gm0 + m0 + i) * 256 + ((gn0 + n0) >> 2)] = o;
    }
}

// ---------------- kernel 3: forward LSTM scan ----------------
// 16 clusters x 8 CTAs, 256 thr. Cluster = 4 batch; CTA = 32 hidden (128 rows).
// Even-row weights in REGISTERS (64 regs/thr), odd-row weights in SMEM
// (skewed, conflict-deg-4). mbarrier-based h exchange (no barrier.cluster in loop).
// Dynamic smem layout (floats):
//   [0..3]            xbar (u64 mbarrier) + pad
//   [4 .. 4+17408)    Wodd[64 rows][4 kq][68]   (68-skew, 64 used)
//   [+2176)           hbuf[2][4 b][4 kq][68]
//   [+512)            gates[4 b][128 rows]
__global__ void __cluster_dims__(8,1,1) __launch_bounds__(256,1)
k_scan(const float* __restrict__ xg, const float* __restrict__ Whh,
       float* __restrict__ hout)
{
    extern __shared__ float sm[];
    float* wodd  = sm + 4;
    float* hbuf  = sm + 4 + 17408;
    float* gates = hbuf + 2176;

    const int tid   = threadIdx.x;
    const int rank  = blockIdx.x & 7;
    const int bg    = blockIdx.x >> 3;
    const int jbase = rank << 5;

    const int rp = tid >> 2;           // 0..63  (row pair)
    const int kq = tid & 3;            // k-quarter
    const int r0 = rp * 2, r1 = r0 + 1;
    const int grow0 = ((r0 >> 5) << 8) + jbase + (r0 & 31);
    const int grow1 = ((r1 >> 5) << 8) + jbase + (r1 & 31);

    const uint32_t xbar_s = (uint32_t)__cvta_generic_to_shared(sm);
    if (tid == 0) {
        asm volatile("mbarrier.init.shared.b64 [%0], 8;" :: "r"(xbar_s) : "memory");
    }

    // even-row weights -> registers (64 floats = 32 ull)
    ull w0[32];
    {
        const float4* p0 = (const float4*)(Whh + (size_t)grow0 * HH + kq * 64);
#pragma unroll
        for (int i = 0; i < 16; ++i) {
            float4 a = p0[i]; w0[2*i] = pk(a.x, a.y); w0[2*i+1] = pk(a.z, a.w);
        }
    }
    // odd-row weights -> smem (thread-private 68-float segment)
    float* wop = wodd + (rp*4 + kq) * 68;
    {
        const float4* p1 = (const float4*)(Whh + (size_t)grow1 * HH + kq * 64);
#pragma unroll
        for (int i = 0; i < 16; ++i) ((float4*)wop)[0 + i] = p1[i];
    }
    for (int i = tid; i < 2176; i += 256) hbuf[i] = 0.f;

    // phase-2 constants (threads 0..127 act as (b2, j2))
    const int b2 = (tid >> 5) & 3;
    const int j2 = tid & 31;
    float creg = 0.f;
    uint32_t ra0[8], ra1[8], rb[8];
    {
        int jg  = jbase + j2;
        int kqj = jg >> 6, idxj = jg & 63;
        uint32_t hb32 = (uint32_t)__cvta_generic_to_shared(hbuf);
        uint32_t o0 = (uint32_t)((((0*4 + b2)*4 + kqj)*68 + idxj) * 4);
        uint32_t o1 = (uint32_t)((((1*4 + b2)*4 + kqj)*68 + idxj) * 4);
#pragma unroll
        for (int r = 0; r < 8; ++r) {
            asm("mapa.shared::cluster.u32 %0, %1, %2;" : "=r"(ra0[r]) : "r"(hb32+o0), "r"(r));
            asm("mapa.shared::cluster.u32 %0, %1, %2;" : "=r"(ra1[r]) : "r"(hb32+o1), "r"(r));
            asm("mapa.shared::cluster.u32 %0, %1, %2;" : "=r"(rb[r])  : "r"(xbar_s),  "r"(r));
        }
    }

    const float* xp0 = xg + (size_t)(4*bg + kq) * NG + grow0;
    const float* xp1 = xg + (size_t)(4*bg + kq) * NG + grow1;
    float nx0 = xp0[0], nx1 = xp1[0];

    __syncthreads();
    asm volatile("barrier.cluster.arrive.aligned;" ::: "memory");
    asm volatile("barrier.cluster.wait.aligned;"   ::: "memory");

#pragma unroll 1
    for (int t = 0; t < SQ; ++t) {
        const float* hq = hbuf + (t & 1) * 1088 + kq * 68;

        ull a00=0,a01=0,a02=0,a03=0, a10=0,a11=0,a12=0,a13=0;
#pragma unroll
        for (int c = 0; c < 16; ++c) {
            ulonglong2 h0 = *(const ulonglong2*)(hq + 0*272 + 4*c);
            ulonglong2 h1 = *(const ulonglong2*)(hq + 1*272 + 4*c);
            ulonglong2 h2 = *(const ulonglong2*)(hq + 2*272 + 4*c);
            ulonglong2 h3 = *(const ulonglong2*)(hq + 3*272 + 4*c);
            ulonglong2 wo = *(const ulonglong2*)(wop + 4*c);
            ull wa = w0[2*c], wb = w0[2*c+1];
            fma2(a00, wa, h0.x); fma2(a00, wb, h0.y);
            fma2(a01, wa, h1.x); fma2(a01, wb, h1.y);
            fma2(a02, wa, h2.x); fma2(a02, wb, h2.y);
            fma2(a03, wa, h3.x); fma2(a03, wb, h3.y);
            fma2(a10, wo.x, h0.x); fma2(a10, wo.y, h0.y);
            fma2(a11, wo.x, h1.x); fma2(a11, wo.y, h1.y);
            fma2(a12, wo.x, h2.x); fma2(a12, wo.y, h2.y);
            fma2(a13, wo.x, h3.x); fma2(a13, wo.y, h3.y);
        }

        float cx0 = nx0, cx1 = nx1;
        if (t + 1 < SQ) {
            nx0 = xp0[(size_t)(t + 1) * (BB * NG)];
            nx1 = xp1[(size_t)(t + 1) * (BB * NG)];
        }

        // cross-kq reduction
        float2 f;
        f = unpk(a00); float s00 = f.x + f.y;
        f = unpk(a01); float s01 = f.x + f.y;
        f = unpk(a02); float s02 = f.x + f.y;
        f = unpk(a03); float s03 = f.x + f.y;
        f = unpk(a10); float s10 = f.x + f.y;
        f = unpk(a11); float s11 = f.x + f.y;
        f = unpk(a12); float s12 = f.x + f.y;
        f = unpk(a13); float s13 = f.x + f.y;
        s00 += __shfl_xor_sync(~0u, s00, 1); s00 += __shfl_xor_sync(~0u, s00, 2);
        s01 += __shfl_xor_sync(~0u, s01, 1); s01 += __shfl_xor_sync(~0u, s01, 2);
        s02 += __shfl_xor_sync(~0u, s02, 1); s02 += __shfl_xor_sync(~0u, s02, 2);
        s03 += __shfl_xor_sync(~0u, s03, 1); s03 += __shfl_xor_sync(~0u, s03, 2);
        s10 += __shfl_xor_sync(~0u, s10, 1); s10 += __shfl_xor_sync(~0u, s10, 2);
        s11 += __shfl_xor_sync(~0u, s11, 1); s11 += __shfl_xor_sync(~0u, s11, 2);
        s12 += __shfl_xor_sync(~0u, s12, 1); s12 += __shfl_xor_sync(~0u, s12, 2);
        s13 += __shfl_xor_sync(~0u, s13, 1); s13 += __shfl_xor_sync(~0u, s13, 2);

        float g0, g1;
        if      (kq == 0) { g0 = s00; g1 = s10; }
        else if (kq == 1) { g0 = s01; g1 = s11; }
        else if (kq == 2) { g0 = s02; g1 = s12; }
        else              { g0 = s03; g1 = s13; }
        *(float2*)&gates[kq*128 + r0] = make_float2(g0 + cx0, g1 + cx1);

        __syncthreads();

        if (tid < 128) {
            float gi = gates[b2*128 +  0 + j2];
            float gf = gates[b2*128 + 32 + j2];
            float gg = gates[b2*128 + 64 + j2];
            float go = gates[b2*128 + 96 + j2];
            float iv = sigf(gi), fv = sigf(gf), cv = tanhf_(gg), ov = sigf(go);
            creg = fv * creg + iv * cv;
            float hv = ov * tanhf_(creg);

            if (t < SQ - 1) {
                const bool useBuf1 = ((t & 1) == 0);
#pragma unroll
                for (int r = 0; r < 8; ++r) {
                    uint32_t ad = useBuf1 ? ra1[r] : ra0[r];
                    asm volatile("st.shared::cluster.f32 [%0], %1;" :: "r"(ad), "f"(hv));
                }
            } else {
                hout[(size_t)(4*bg + b2) * HH + jbase + j2] = hv;
            }
        }

        if (t < SQ - 1) {
            __syncthreads();   // all phase-2 stores issued before the arrive
            if (tid == 0) {
#pragma unroll
                for (int r = 0; r < 8; ++r)
                    asm volatile("mbarrier.arrive.release.cluster.shared::cluster.b64 _, [%0];"
                                 :: "r"(rb[r]) : "memory");
            }
            const uint32_t par = (uint32_t)(t & 1);
            asm volatile(
                "{\n\t.reg .pred P;\n"
                "WAITLP%=:\n\t"
                "mbarrier.try_wait.parity.acquire.cluster.shared::cta.b64 P, [%0], %1, 0x989680;\n\t"
                "@!P bra WAITLP%=;\n\t}"
                :: "r"(xbar_s), "r"(par) : "memory");
        }
    }
}

// ---------------- kernel 4: backward first-step (h0=c0=0) ----------------
__global__ void k_hback(const float* __restrict__ gb, float* __restrict__ hb)
{
    int i = blockIdx.x * 256 + threadIdx.x;
    int b = i >> 8, j = i & 255;
    const float* g = gb + (size_t)b * NG;
    float iv = sigf(g[j]);
    float gv = tanhf_(g[512 + j]);
    float ov = sigf(g[768 + j]);
    float c  = iv * gv;
    hb[i] = ov * tanhf_(c);
}

// ---------------- kernel 5: output head (warp per batch elem) ----------------
__global__ void k_out(const float* __restrict__ hf, const float* __restrict__ hb,
                      const float* __restrict__ Wout, const float* __restrict__ bout,
                      float* __restrict__ out)
{
    int b = blockIdx.x, lane = threadIdx.x;
    const float4* hf4 = (const float4*)(hf + (size_t)b * HH);
    const float4* hb4 = (const float4*)(hb + (size_t)b * HH);
    const float4* wA  = (const float4*)Wout;
    const float4* wB  = (const float4*)(Wout + HH);
    float acc = 0.f;
#pragma unroll
    for (int i = 0; i < 2; ++i) {
        int idx = lane + 32*i;
        float4 a = hf4[idx], w = wA[idx];
        acc += a.x*w.x + a.y*w.y + a.z*w.z + a.w*w.w;
        float4 c = hb4[idx], v = wB[idx];
        acc += c.x*v.x + c.y*v.y + c.z*v.z + c.w*v.w;
    }
#pragma unroll
    for (int o = 16; o; o >>= 1) acc += __shfl_xor_sync(~0u, acc, o);
    if (lane == 0) out[b] = sigf(acc + bout[0]);
}

// ---------------- launch ----------------
extern "C" void kernel_launch(void* const* d_in, const int* in_sizes, int n_in,
                              void* d_out, int out_size)
{
    (void)in_sizes; (void)n_in; (void)out_size;
    const int*   seq  = (const int*)  d_in[0];
    const float* emb  = (const float*)d_in[1];
    const float* Wihf = (const float*)d_in[2];
    const float* Whhf = (const float*)d_in[3];
    const float* bf   = (const float*)d_in[4];
    const float* Wihb = (const float*)d_in[5];
    const float* Whhb = (const float*)d_in[6];
    const float* bb   = (const float*)d_in[7];
    const float* Wout = (const float*)d_in[8];
    const float* bout = (const float*)d_in[9];
    (void)Whhb;
    float* out = (float*)d_out;

    float *x, *xgf, *gb, *hf, *hb;
    cudaGetSymbolAddress((void**)&x,   g_x);
    cudaGetSymbolAddress((void**)&xgf, g_xg);
    cudaGetSymbolAddress((void**)&gb,  g_gb);
    cudaGetSymbolAddress((void**)&hf,  g_hf);
    cudaGetSymbolAddress((void**)&hb,  g_hb);

    const int SMEM_GEMM = 2 * 128 * 68 * 4;                     // 69632
    const int SMEM_SCAN = (4 + 17408 + 2176 + 512) * 4;         // 80400
    cudaFuncSetAttribute(k_gemm, cudaFuncAttributeMaxDynamicSharedMemorySize, SMEM_GEMM);
    cudaFuncSetAttribute(k_scan, cudaFuncAttributeMaxDynamicSharedMemorySize, SMEM_SCAN);

    // order chosen so k_scan lands in ncu's profiled launch slot (#4)
    k_embed<<<SQ*BB/4, 128>>>(seq, emb, x);
    dim3 g2(16, SQ*BB/64);
    k_gemm<<<g2, 256, SMEM_GEMM>>>(x, Wihf, bf, xgf);
    dim3 g2b(16, 1);
    k_gemm<<<g2b, 256, SMEM_GEMM>>>(x + (size_t)(SQ-1)*BB*EE, Wihb, bb, gb);
    k_scan<<<128, 256, SMEM_SCAN>>>(xgf, Whhf, hf);
    k_hback<<<64, 256>>>(gb, hb);
    k_out<<<64, 32>>>(hf, hb, Wout, bout, out);
}

// round 9
// speedup vs baseline: 2.5226x; 2.5226x over previous
#include <cuda_runtime.h>
#include <cstdint>
#include <cstring>

#define SQ 512
#define BB 64
#define EE 128
#define HH 256
#define NG 1024   // 4*H

// ---------------- scratch (static device memory; no allocations) ----------------
__device__ float g_x [SQ*BB*EE];          // embedded inputs          16 MB
__device__ float g_xg[(size_t)SQ*BB*NG];  // forward input-gate proj  128 MB
__device__ float g_gb[BB*NG];             // backward first-step gates
__device__ float g_hf[BB*HH];             // final forward h
__device__ float g_hb[BB*HH];             // backward first-step h

typedef unsigned long long ull;

__device__ __forceinline__ void fma2(ull& d, ull a, ull b) {
    asm("fma.rn.f32x2 %0, %1, %2, %0;" : "+l"(d) : "l"(a), "l"(b));
}
__device__ __forceinline__ ull pk(float x, float y) {
    float2 f = make_float2(x, y); ull v; memcpy(&v, &f, 8); return v;
}
__device__ __forceinline__ float2 unpk(ull v) {
    float2 f; memcpy(&f, &v, 8); return f;
}
__device__ __forceinline__ float sigf(float x)  { return 1.f/(1.f+__expf(-x)); }
__device__ __forceinline__ float tanhf_(float x){ return 1.f - 2.f/(__expf(2.f*x)+1.f); }

// ---------------- kernel 1: embedding gather ----------------
__global__ void k_embed(const int* __restrict__ seq, const float* __restrict__ emb,
                        float* __restrict__ x)
{
    int row  = blockIdx.x * 4 + (threadIdx.x >> 5);
    int lane = threadIdx.x & 31;
    int idx  = seq[row];
    float4 v;
    if (idx == 0) v = make_float4(0.f, 0.f, 0.f, 0.f);
    else          v = ((const float4*)emb)[(size_t)idx * 32 + lane];
    ((float4*)x)[(size_t)row * 32 + lane] = v;
}

// ---------------- kernel 2: C[M,1024] = A[M,128] @ W[1024,128]^T + bias ----------------
__global__ void __launch_bounds__(256)
k_gemm(const float* __restrict__ A, const float* __restrict__ W,
       const float* __restrict__ bias, float* __restrict__ C)
{
    extern __shared__ float sm[];
    float* As = sm;             // [128][68]
    float* Bs = sm + 128*68;    // [128][68]

    const int tid = threadIdx.x;
    const int gm0 = blockIdx.y * 64;
    const int gn0 = blockIdx.x * 64;

#pragma unroll
    for (int i = 0; i < 8; ++i) {
        int e   = tid + i * 256;
        int row = e >> 5;
        int kq  = e & 31;
        float4 a = ((const float4*)A)[(size_t)(gm0 + row) * 32 + kq];
        As[(4*kq+0)*68 + row] = a.x;
        As[(4*kq+1)*68 + row] = a.y;
        As[(4*kq+2)*68 + row] = a.z;
        As[(4*kq+3)*68 + row] = a.w;
        float4 w = ((const float4*)W)[(size_t)(gn0 + row) * 32 + kq];
        Bs[(4*kq+0)*68 + row] = w.x;
        Bs[(4*kq+1)*68 + row] = w.y;
        Bs[(4*kq+2)*68 + row] = w.z;
        Bs[(4*kq+3)*68 + row] = w.w;
    }
    __syncthreads();

    const int tx = tid & 15, ty = tid >> 4;
    const int m0 = ty * 4, n0 = tx * 4;

    float b0 = bias[gn0+n0+0], b1 = bias[gn0+n0+1];
    float b2 = bias[gn0+n0+2], b3 = bias[gn0+n0+3];
    ull acc[4][2];
#pragma unroll
    for (int i = 0; i < 4; ++i) { acc[i][0] = pk(b0,b1); acc[i][1] = pk(b2,b3); }

#pragma unroll 4
    for (int k = 0; k < 128; ++k) {
        float4 a4 = *(const float4*)&As[k*68 + m0];
        ulonglong2 bb = *(const ulonglong2*)&Bs[k*68 + n0];
        ull ad;
        ad = pk(a4.x, a4.x); fma2(acc[0][0], ad, bb.x); fma2(acc[0][1], ad, bb.y);
        ad = pk(a4.y, a4.y); fma2(acc[1][0], ad, bb.x); fma2(acc[1][1], ad, bb.y);
        ad = pk(a4.z, a4.z); fma2(acc[2][0], ad, bb.x); fma2(acc[2][1], ad, bb.y);
        ad = pk(a4.w, a4.w); fma2(acc[3][0], ad, bb.x); fma2(acc[3][1], ad, bb.y);
    }

#pragma unroll
    for (int i = 0; i < 4; ++i) {
        float2 lo = unpk(acc[i][0]), hi = unpk(acc[i][1]);
        float4 o = make_float4(lo.x, lo.y, hi.x, hi.y);
        ((float4*)C)[(size_t)(gm0 + m0 + i) * 256 + ((gn0 + n0) >> 2)] = o;
    }
}

// ---------------- kernel 3: forward LSTM scan ----------------
// 32 clusters x 4 CTAs, 256 thr. Cluster = 2 batch; CTA = 64 hidden units
// (256 gate rows). Gate rows i,f in REGISTERS; g,o in conflict-free SMEM.
// Thread = (rp = hidden unit 0..63, kq = k-quarter 0..3); after the shfl
// reduce, lane kq owns gate kq. h exchange: warp 0 pushes the CTA's 64-unit
// slice to all 4 CTAs as 128B-wide cluster stores. Sync = barrier.cluster.
//
// Dyn smem (floats):
//   wgs  [16c][256tid][4]  16384   (gate 2 weights, conflict-free)
//   wos  [16c][256tid][4]  16384   (gate 3)
//   hbuf [2 buf][2 b][272] 1088    (h slices at kq*68, CTA rank -> seg rank)
//   gates[2 b][4 g][65]    520
//   hstage[128]            128
__global__ void __cluster_dims__(4,1,1) __launch_bounds__(256,1)
k_scan(const float* __restrict__ xg, const float* __restrict__ Whh,
       float* __restrict__ hout)
{
    extern __shared__ float sm[];
    float* wgs    = sm;
    float* wos    = sm + 16384;
    float* hbuf   = sm + 32768;
    float* gates  = hbuf + 1088;
    float* hstage = gates + 520;

    const int tid   = threadIdx.x;
    const int rank  = blockIdx.x & 3;
    const int bg    = blockIdx.x >> 2;        // 0..31  (2 batch elems each)
    const int jbase = rank << 6;              // 64-unit hidden slice

    const int rp = tid >> 2;                  // hidden unit 0..63
    const int kq = tid & 3;                   // k in [64*kq, 64*kq+64)

    // ---- weights: i,f rows -> regs; g,o rows -> smem [c][tid] ----
    ull wi[32], wf[32];
    {
        const float4* pi = (const float4*)(Whh + (size_t)(0*HH + jbase + rp)*HH + kq*64);
        const float4* pf = (const float4*)(Whh + (size_t)(1*HH + jbase + rp)*HH + kq*64);
        const float4* pg = (const float4*)(Whh + (size_t)(2*HH + jbase + rp)*HH + kq*64);
        const float4* po = (const float4*)(Whh + (size_t)(3*HH + jbase + rp)*HH + kq*64);
#pragma unroll
        for (int c = 0; c < 16; ++c) {
            float4 a = pi[c]; wi[2*c] = pk(a.x, a.y); wi[2*c+1] = pk(a.z, a.w);
            float4 b = pf[c]; wf[2*c] = pk(b.x, b.y); wf[2*c+1] = pk(b.z, b.w);
            ((float4*)wgs)[c*256 + tid] = pg[c];
            ((float4*)wos)[c*256 + tid] = po[c];
        }
    }
    for (int i = tid; i < 1088; i += 256) hbuf[i] = 0.f;

    // ---- phase-2 identity (threads 0..127): b2 = tid>>6, j2 = tid&63 ----
    const int b2 = tid >> 6;
    const int j2 = tid & 63;
    float creg = 0.f;

    // ---- warp0 push addresses (lane l: b = l>>4, idx4 = (l&15)*4) ----
    uint32_t ad0[4], ad1[4];
    if (tid < 32) {
        int pb   = tid >> 4;
        int idx4 = (tid & 15) * 4;
        uint32_t hb32 = (uint32_t)__cvta_generic_to_shared(hbuf);
        uint32_t o0 = (uint32_t)((0*544 + pb*272 + rank*68 + idx4) * 4);
        uint32_t o1 = (uint32_t)((1*544 + pb*272 + rank*68 + idx4) * 4);
#pragma unroll
        for (int r = 0; r < 4; ++r) {
            asm("mapa.shared::cluster.u32 %0, %1, %2;" : "=r"(ad0[r]) : "r"(hb32+o0), "r"(r));
            asm("mapa.shared::cluster.u32 %0, %1, %2;" : "=r"(ad1[r]) : "r"(hb32+o1), "r"(r));
        }
    }

    // xg pointers: lane kq handles gate kq for its hidden unit, both batches
    const float* xp0 = xg + (size_t)(2*bg + 0) * NG + kq*HH + jbase + rp;
    const float* xp1 = xg + (size_t)(2*bg + 1) * NG + kq*HH + jbase + rp;
    float nx0 = xp0[0], nx1 = xp1[0];

    __syncthreads();
    asm volatile("barrier.cluster.arrive.aligned;" ::: "memory");
    asm volatile("barrier.cluster.wait.aligned;"   ::: "memory");

#pragma unroll 1
    for (int t = 0; t < SQ; ++t) {
        const float* hq = hbuf + (t & 1) * 544 + kq * 68;

        ull ai0=0,ai1=0, af0=0,af1=0, ag0=0,ag1=0, ao0=0,ao1=0;
#pragma unroll
        for (int c = 0; c < 16; ++c) {
            ulonglong2 h0 = *(const ulonglong2*)(hq + 4*c);
            ulonglong2 h1 = *(const ulonglong2*)(hq + 272 + 4*c);
            ulonglong2 wg = ((const ulonglong2*)wgs)[c*256 + tid];
            ulonglong2 wo = ((const ulonglong2*)wos)[c*256 + tid];
            ull ia = wi[2*c], ib = wi[2*c+1], fa = wf[2*c], fb = wf[2*c+1];
            fma2(ai0, ia, h0.x); fma2(ai0, ib, h0.y);
            fma2(ai1, ia, h1.x); fma2(ai1, ib, h1.y);
            fma2(af0, fa, h0.x); fma2(af0, fb, h0.y);
            fma2(af1, fa, h1.x); fma2(af1, fb, h1.y);
            fma2(ag0, wg.x, h0.x); fma2(ag0, wg.y, h0.y);
            fma2(ag1, wg.x, h1.x); fma2(ag1, wg.y, h1.y);
            fma2(ao0, wo.x, h0.x); fma2(ao0, wo.y, h0.y);
            fma2(ao1, wo.x, h1.x); fma2(ao1, wo.y, h1.y);
        }

        float cx0 = nx0, cx1 = nx1;
        if (t + 1 < SQ) {
            nx0 = xp0[(size_t)(t + 1) * (BB * NG)];
            nx1 = xp1[(size_t)(t + 1) * (BB * NG)];
        }

        // reduce over the 4 kq lanes (lane bits 0-1)
        float2 f;
        f = unpk(ai0); float si0 = f.x + f.y;
        f = unpk(ai1); float si1 = f.x + f.y;
        f = unpk(af0); float sf0 = f.x + f.y;
        f = unpk(af1); float sf1 = f.x + f.y;
        f = unpk(ag0); float sg0 = f.x + f.y;
        f = unpk(ag1); float sg1 = f.x + f.y;
        f = unpk(ao0); float so0 = f.x + f.y;
        f = unpk(ao1); float so1 = f.x + f.y;
        si0 += __shfl_xor_sync(~0u, si0, 1); si0 += __shfl_xor_sync(~0u, si0, 2);
        si1 += __shfl_xor_sync(~0u, si1, 1); si1 += __shfl_xor_sync(~0u, si1, 2);
        sf0 += __shfl_xor_sync(~0u, sf0, 1); sf0 += __shfl_xor_sync(~0u, sf0, 2);
        sf1 += __shfl_xor_sync(~0u, sf1, 1); sf1 += __shfl_xor_sync(~0u, sf1, 2);
        sg0 += __shfl_xor_sync(~0u, sg0, 1); sg0 += __shfl_xor_sync(~0u, sg0, 2);
        sg1 += __shfl_xor_sync(~0u, sg1, 1); sg1 += __shfl_xor_sync(~0u, sg1, 2);
        so0 += __shfl_xor_sync(~0u, so0, 1); so0 += __shfl_xor_sync(~0u, so0, 2);
        so1 += __shfl_xor_sync(~0u, so1, 1); so1 += __shfl_xor_sync(~0u, so1, 2);

        float g0, g1;
        if      (kq == 0) { g0 = si0; g1 = si1; }
        else if (kq == 1) { g0 = sf0; g1 = sf1; }
        else if (kq == 2) { g0 = sg0; g1 = sg1; }
        else              { g0 = so0; g1 = so1; }
        gates[0*260 + kq*65 + rp] = g0 + cx0;
        gates[1*260 + kq*65 + rp] = g1 + cx1;

        __syncthreads();

        if (tid < 128) {
            float gi = gates[b2*260 +   0 + j2];
            float gf = gates[b2*260 +  65 + j2];
            float gg = gates[b2*260 + 130 + j2];
            float go = gates[b2*260 + 195 + j2];
            float iv = sigf(gi), fv = sigf(gf), cv = tanhf_(gg), ov = sigf(go);
            creg = fv * creg + iv * cv;
            float hv = ov * tanhf_(creg);
            hstage[tid] = hv;
            if (t == SQ - 1)
                hout[(size_t)(2*bg + b2) * HH + jbase + j2] = hv;
        }

        if (t < SQ - 1) {
            __syncthreads();
            if (tid < 32) {
                float4 v = ((const float4*)hstage)[tid];
                ull p0 = pk(v.x, v.y), p1 = pk(v.z, v.w);
                const bool useBuf1 = ((t & 1) == 0);
#pragma unroll
                for (int r = 0; r < 4; ++r) {
                    uint32_t a = useBuf1 ? ad1[r] : ad0[r];
                    asm volatile("st.shared::cluster.b64 [%0], %1;"     :: "r"(a),   "l"(p0) : "memory");
                    asm volatile("st.shared::cluster.b64 [%0+8], %1;"   :: "r"(a),   "l"(p1) : "memory");
                }
            }
            asm volatile("barrier.cluster.arrive.aligned;" ::: "memory");
            asm volatile("barrier.cluster.wait.aligned;"   ::: "memory");
        }
    }
}

// ---------------- kernel 4: backward first-step (h0=c0=0) ----------------
__global__ void k_hback(const float* __restrict__ gb, float* __restrict__ hb)
{
    int i = blockIdx.x * 256 + threadIdx.x;
    int b = i >> 8, j = i & 255;
    const float* g = gb + (size_t)b * NG;
    float iv = sigf(g[j]);
    float gv = tanhf_(g[512 + j]);
    float ov = sigf(g[768 + j]);
    float c  = iv * gv;
    hb[i] = ov * tanhf_(c);
}

// ---------------- kernel 5: output head (warp per batch elem) ----------------
__global__ void k_out(const float* __restrict__ hf, const float* __restrict__ hb,
                      const float* __restrict__ Wout, const float* __restrict__ bout,
                      float* __restrict__ out)
{
    int b = blockIdx.x, lane = threadIdx.x;
    const float4* hf4 = (const float4*)(hf + (size_t)b * HH);
    const float4* hb4 = (const float4*)(hb + (size_t)b * HH);
    const float4* wA  = (const float4*)Wout;
    const float4* wB  = (const float4*)(Wout + HH);
    float acc = 0.f;
#pragma unroll
    for (int i = 0; i < 2; ++i) {
        int idx = lane + 32*i;
        float4 a = hf4[idx], w = wA[idx];
        acc += a.x*w.x + a.y*w.y + a.z*w.z + a.w*w.w;
        float4 c = hb4[idx], v = wB[idx];
        acc += c.x*v.x + c.y*v.y + c.z*v.z + c.w*v.w;
    }
#pragma unroll
    for (int o = 16; o; o >>= 1) acc += __shfl_xor_sync(~0u, acc, o);
    if (lane == 0) out[b] = sigf(acc + bout[0]);
}

// ---------------- launch ----------------
extern "C" void kernel_launch(void* const* d_in, const int* in_sizes, int n_in,
                              void* d_out, int out_size)
{
    (void)in_sizes; (void)n_in; (void)out_size;
    const int*   seq  = (const int*)  d_in[0];
    const float* emb  = (const float*)d_in[1];
    const float* Wihf = (const float*)d_in[2];
    const float* Whhf = (const float*)d_in[3];
    const float* bf   = (const float*)d_in[4];
    const float* Wihb = (const float*)d_in[5];
    const float* Whhb = (const float*)d_in[6];
    const float* bb   = (const float*)d_in[7];
    const float* Wout = (const float*)d_in[8];
    const float* bout = (const float*)d_in[9];
    (void)Whhb;
    float* out = (float*)d_out;

    float *x, *xgf, *gb, *hf, *hb;
    cudaGetSymbolAddress((void**)&x,   g_x);
    cudaGetSymbolAddress((void**)&xgf, g_xg);
    cudaGetSymbolAddress((void**)&gb,  g_gb);
    cudaGetSymbolAddress((void**)&hf,  g_hf);
    cudaGetSymbolAddress((void**)&hb,  g_hb);

    const int SMEM_GEMM = 2 * 128 * 68 * 4;                         // 69632
    const int SMEM_SCAN = (16384*2 + 1088 + 520 + 128) * 4;         // 138016
    cudaFuncSetAttribute(k_gemm, cudaFuncAttributeMaxDynamicSharedMemorySize, SMEM_GEMM);
    cudaFuncSetAttribute(k_scan, cudaFuncAttributeMaxDynamicSharedMemorySize, SMEM_SCAN);

    k_embed<<<SQ*BB/4, 128>>>(seq, emb, x);
    dim3 g2(16, SQ*BB/64);
    k_gemm<<<g2, 256, SMEM_GEMM>>>(x, Wihf, bf, xgf);
    dim3 g2b(16, 1);
    k_gemm<<<g2b, 256, SMEM_GEMM>>>(x + (size_t)(SQ-1)*BB*EE, Wihb, bb, gb);
    k_scan<<<128, 256, SMEM_SCAN>>>(xgf, Whhf, hf);
    k_hback<<<64, 256>>>(gb, hb);
    k_out<<<64, 32>>>(hf, hb, Wout, bout, out);
}

// round 10
// speedup vs baseline: 2.5565x; 1.0134x over previous
#include <cuda_runtime.h>
#include <cstdint>
#include <cstring>

#define SQ 512
#define BB 64
#define EE 128
#define HH 256
#define NG 1024   // 4*H

// ---------------- scratch (static device memory; no allocations) ----------------
__device__ float g_x [SQ*BB*EE];          // embedded inputs          16 MB
__device__ float g_xg[(size_t)SQ*BB*NG];  // forward input-gate proj  128 MB
__device__ float g_gb[BB*NG];             // backward first-step gates
__device__ float g_hf[BB*HH];             // final forward h
__device__ float g_hb[BB*HH];             // backward first-step h

typedef unsigned long long ull;

__device__ __forceinline__ void fma2(ull& d, ull a, ull b) {
    asm("fma.rn.f32x2 %0, %1, %2, %0;" : "+l"(d) : "l"(a), "l"(b));
}
__device__ __forceinline__ ull pk(float x, float y) {
    float2 f = make_float2(x, y); ull v; memcpy(&v, &f, 8); return v;
}
__device__ __forceinline__ float2 unpk(ull v) {
    float2 f; memcpy(&f, &v, 8); return f;
}
__device__ __forceinline__ float sigf(float x)  { return 1.f/(1.f+__expf(-x)); }
__device__ __forceinline__ float tanhf_(float x){ return 1.f - 2.f/(__expf(2.f*x)+1.f); }

// ---------------- kernel 1: embedding gather ----------------
__global__ void k_embed(const int* __restrict__ seq, const float* __restrict__ emb,
                        float* __restrict__ x)
{
    int row  = blockIdx.x * 4 + (threadIdx.x >> 5);
    int lane = threadIdx.x & 31;
    int idx  = seq[row];
    float4 v;
    if (idx == 0) v = make_float4(0.f, 0.f, 0.f, 0.f);
    else          v = ((const float4*)emb)[(size_t)idx * 32 + lane];
    ((float4*)x)[(size_t)row * 32 + lane] = v;
}

// ---------------- kernel 2: C[M,1024] = A[M,128] @ W[1024,128]^T + bias ----------------
__global__ void __launch_bounds__(256)
k_gemm(const float* __restrict__ A, const float* __restrict__ W,
       const float* __restrict__ bias, float* __restrict__ C)
{
    extern __shared__ float sm[];
    float* As = sm;             // [128][68]
    float* Bs = sm + 128*68;    // [128][68]

    const int tid = threadIdx.x;
    const int gm0 = blockIdx.y * 64;
    const int gn0 = blockIdx.x * 64;

#pragma unroll
    for (int i = 0; i < 8; ++i) {
        int e   = tid + i * 256;
        int row = e >> 5;
        int kq  = e & 31;
        float4 a = ((const float4*)A)[(size_t)(gm0 + row) * 32 + kq];
        As[(4*kq+0)*68 + row] = a.x;
        As[(4*kq+1)*68 + row] = a.y;
        As[(4*kq+2)*68 + row] = a.z;
        As[(4*kq+3)*68 + row] = a.w;
        float4 w = ((const float4*)W)[(size_t)(gn0 + row) * 32 + kq];
        Bs[(4*kq+0)*68 + row] = w.x;
        Bs[(4*kq+1)*68 + row] = w.y;
        Bs[(4*kq+2)*68 + row] = w.z;
        Bs[(4*kq+3)*68 + row] = w.w;
    }
    __syncthreads();

    const int tx = tid & 15, ty = tid >> 4;
    const int m0 = ty * 4, n0 = tx * 4;

    float b0 = bias[gn0+n0+0], b1 = bias[gn0+n0+1];
    float b2 = bias[gn0+n0+2], b3 = bias[gn0+n0+3];
    ull acc[4][2];
#pragma unroll
    for (int i = 0; i < 4; ++i) { acc[i][0] = pk(b0,b1); acc[i][1] = pk(b2,b3); }

#pragma unroll 4
    for (int k = 0; k < 128; ++k) {
        float4 a4 = *(const float4*)&As[k*68 + m0];
        ulonglong2 bb = *(const ulonglong2*)&Bs[k*68 + n0];
        ull ad;
        ad = pk(a4.x, a4.x); fma2(acc[0][0], ad, bb.x); fma2(acc[0][1], ad, bb.y);
        ad = pk(a4.y, a4.y); fma2(acc[1][0], ad, bb.x); fma2(acc[1][1], ad, bb.y);
        ad = pk(a4.z, a4.z); fma2(acc[2][0], ad, bb.x); fma2(acc[2][1], ad, bb.y);
        ad = pk(a4.w, a4.w); fma2(acc[3][0], ad, bb.x); fma2(acc[3][1], ad, bb.y);
    }

#pragma unroll
    for (int i = 0; i < 4; ++i) {
        float2 lo = unpk(acc[i][0]), hi = unpk(acc[i][1]);
        float4 o = make_float4(lo.x, lo.y, hi.x, hi.y);
        ((float4*)C)[(size_t)(gm0 + m0 + i) * 256 + ((gn0 + n0) >> 2)] = o;
    }
}

// ---------------- kernel 3: forward LSTM scan ----------------
// 32 clusters x 4 CTAs, 256 thr. Cluster = 2 batch; CTA = 64 hidden units.
// Gate rows i,f in registers; g,o in conflict-free SMEM.
// NO intra-step __syncthreads / staging: the shfl butterfly leaves the full
// 4-gate sums (xg folded in pre-butterfly) in EVERY lane of each 4-lane group;
// each lane runs phase-2 redundantly for batch kq&1 and pushes its h to 2 of
// the 4 CTAs (kq<2 -> ranks 0,1; kq>=2 -> ranks 2,3). Split cluster barrier:
// arrive after push (xg prefetch in its shadow), wait at top of next step.
//
// Dyn smem (floats): wgs 16384 | wos 16384 | hbuf[2][2][272] 1088
__global__ void __cluster_dims__(4,1,1) __launch_bounds__(256,1)
k_scan(const float* __restrict__ xg, const float* __restrict__ Whh,
       float* __restrict__ hout)
{
    extern __shared__ float sm[];
    float* wgs  = sm;
    float* wos  = sm + 16384;
    float* hbuf = sm + 32768;

    const int tid   = threadIdx.x;
    const int rank  = blockIdx.x & 3;
    const int bg    = blockIdx.x >> 2;        // 0..31  (2 batch elems each)
    const int jbase = rank << 6;              // 64-unit hidden slice

    const int rp = tid >> 2;                  // hidden unit 0..63
    const int kq = tid & 3;                   // k in [64*kq, 64*kq+64)

    // ---- weights: i,f rows -> regs; g,o rows -> smem [c][tid] ----
    ull wi[32], wf[32];
    {
        const float4* pi = (const float4*)(Whh + (size_t)(0*HH + jbase + rp)*HH + kq*64);
        const float4* pf = (const float4*)(Whh + (size_t)(1*HH + jbase + rp)*HH + kq*64);
        const float4* pg = (const float4*)(Whh + (size_t)(2*HH + jbase + rp)*HH + kq*64);
        const float4* po = (const float4*)(Whh + (size_t)(3*HH + jbase + rp)*HH + kq*64);
#pragma unroll
        for (int c = 0; c < 16; ++c) {
            float4 a = pi[c]; wi[2*c] = pk(a.x, a.y); wi[2*c+1] = pk(a.z, a.w);
            float4 b = pf[c]; wf[2*c] = pk(b.x, b.y); wf[2*c+1] = pk(b.z, b.w);
            ((float4*)wgs)[c*256 + tid] = pg[c];
            ((float4*)wos)[c*256 + tid] = po[c];
        }
    }
    for (int i = tid; i < 1088; i += 256) hbuf[i] = 0.f;

    // ---- per-thread phase-2 identity: batch b = kq&1, unit rp ----
    const int pb = kq & 1;
    float creg = 0.f;

    // push addresses: 2 destination ranks, both buffers
    uint32_t pa0[2], pa1[2];
    {
        uint32_t hb32 = (uint32_t)__cvta_generic_to_shared(hbuf);
        uint32_t o0 = (uint32_t)(((0*2 + pb)*272 + rank*68 + rp) * 4);  // buffer 0
        uint32_t o1 = (uint32_t)(((1*2 + pb)*272 + rank*68 + rp) * 4);  // buffer 1
        int d0 = (kq < 2) ? 0 : 2;
#pragma unroll
        for (int r = 0; r < 2; ++r) {
            asm("mapa.shared::cluster.u32 %0, %1, %2;" : "=r"(pa0[r]) : "r"(hb32+o0), "r"(d0+r));
            asm("mapa.shared::cluster.u32 %0, %1, %2;" : "=r"(pa1[r]) : "r"(hb32+o1), "r"(d0+r));
        }
    }

    // xg pointers: lane kq loads gate-kq xg for its hidden unit, both batches
    const float* xp0 = xg + (size_t)(2*bg + 0) * NG + kq*HH + jbase + rp;
    const float* xp1 = xg + (size_t)(2*bg + 1) * NG + kq*HH + jbase + rp;
    float nx0 = xp0[0], nx1 = xp1[0];

    __syncthreads();
    asm volatile("barrier.cluster.arrive.aligned;" ::: "memory");
    asm volatile("barrier.cluster.wait.aligned;"   ::: "memory");

#pragma unroll 1
    for (int t = 0; t < SQ; ++t) {
        if (t) asm volatile("barrier.cluster.wait.aligned;" ::: "memory");

        const float* hq = hbuf + (t & 1) * 544 + kq * 68;

        ull ai0=0,ai1=0, af0=0,af1=0, ag0=0,ag1=0, ao0=0,ao1=0;
#pragma unroll
        for (int c = 0; c < 16; ++c) {
            ulonglong2 h0 = *(const ulonglong2*)(hq + 4*c);
            ulonglong2 h1 = *(const ulonglong2*)(hq + 272 + 4*c);
            ulonglong2 wg = ((const ulonglong2*)wgs)[c*256 + tid];
            ulonglong2 wo = ((const ulonglong2*)wos)[c*256 + tid];
            ull ia = wi[2*c], ib = wi[2*c+1], fa = wf[2*c], fb = wf[2*c+1];
            fma2(ai0, ia, h0.x); fma2(ai0, ib, h0.y);
            fma2(ai1, ia, h1.x); fma2(ai1, ib, h1.y);
            fma2(af0, fa, h0.x); fma2(af0, fb, h0.y);
            fma2(af1, fa, h1.x); fma2(af1, fb, h1.y);
            fma2(ag0, wg.x, h0.x); fma2(ag0, wg.y, h0.y);
            fma2(ag1, wg.x, h1.x); fma2(ag1, wg.y, h1.y);
            fma2(ao0, wo.x, h0.x); fma2(ao0, wo.y, h0.y);
            fma2(ao1, wo.x, h1.x); fma2(ao1, wo.y, h1.y);
        }

        // pairwise collapse + fold xg into own gate's sums (pre-butterfly)
        float2 f;
        f = unpk(ai0); float si0 = f.x + f.y;
        f = unpk(ai1); float si1 = f.x + f.y;
        f = unpk(af0); float sf0 = f.x + f.y;
        f = unpk(af1); float sf1 = f.x + f.y;
        f = unpk(ag0); float sg0 = f.x + f.y;
        f = unpk(ag1); float sg1 = f.x + f.y;
        f = unpk(ao0); float so0 = f.x + f.y;
        f = unpk(ao1); float so1 = f.x + f.y;
        if      (kq == 0) { si0 += nx0; si1 += nx1; }
        else if (kq == 1) { sf0 += nx0; sf1 += nx1; }
        else if (kq == 2) { sg0 += nx0; sg1 += nx1; }
        else              { so0 += nx0; so1 += nx1; }

        // butterfly: afterwards EVERY lane of the 4-group has all 8 full sums
        si0 += __shfl_xor_sync(~0u, si0, 1); si0 += __shfl_xor_sync(~0u, si0, 2);
        si1 += __shfl_xor_sync(~0u, si1, 1); si1 += __shfl_xor_sync(~0u, si1, 2);
        sf0 += __shfl_xor_sync(~0u, sf0, 1); sf0 += __shfl_xor_sync(~0u, sf0, 2);
        sf1 += __shfl_xor_sync(~0u, sf1, 1); sf1 += __shfl_xor_sync(~0u, sf1, 2);
        sg0 += __shfl_xor_sync(~0u, sg0, 1); sg0 += __shfl_xor_sync(~0u, sg0, 2);
        sg1 += __shfl_xor_sync(~0u, sg1, 1); sg1 += __shfl_xor_sync(~0u, sg1, 2);
        so0 += __shfl_xor_sync(~0u, so0, 1); so0 += __shfl_xor_sync(~0u, so0, 2);
        so1 += __shfl_xor_sync(~0u, so1, 1); so1 += __shfl_xor_sync(~0u, so1, 2);

        // phase 2 (redundant copy per kq pair), batch pb = kq&1
        float gi = pb ? si1 : si0;
        float gf = pb ? sf1 : sf0;
        float gg = pb ? sg1 : sg0;
        float go = pb ? so1 : so0;
        float iv = sigf(gi), fv = sigf(gf), cv = tanhf_(gg), ov = sigf(go);
        creg = fv * creg + iv * cv;
        float hv = ov * tanhf_(creg);

        if (t < SQ - 1) {
            const bool useBuf1 = ((t & 1) == 0);
            uint32_t a0 = useBuf1 ? pa1[0] : pa0[0];
            uint32_t a1 = useBuf1 ? pa1[1] : pa0[1];
            asm volatile("st.shared::cluster.f32 [%0], %1;" :: "r"(a0), "f"(hv) : "memory");
            asm volatile("st.shared::cluster.f32 [%0], %1;" :: "r"(a1), "f"(hv) : "memory");
            asm volatile("barrier.cluster.arrive.aligned;" ::: "memory");
            // prefetch next xg in the barrier's shadow
            nx0 = xp0[(size_t)(t + 1) * (BB * NG)];
            nx1 = xp1[(size_t)(t + 1) * (BB * NG)];
        } else {
            if (kq < 2)
                hout[(size_t)(2*bg + pb) * HH + jbase + rp] = hv;
        }
    }
}

// ---------------- kernel 4: backward first-step (h0=c0=0) ----------------
__global__ void k_hback(const float* __restrict__ gb, float* __restrict__ hb)
{
    int i = blockIdx.x * 256 + threadIdx.x;
    int b = i >> 8, j = i & 255;
    const float* g = gb + (size_t)b * NG;
    float iv = sigf(g[j]);
    float gv = tanhf_(g[512 + j]);
    float ov = sigf(g[768 + j]);
    float c  = iv * gv;
    hb[i] = ov * tanhf_(c);
}

// ---------------- kernel 5: output head (warp per batch elem) ----------------
__global__ void k_out(const float* __restrict__ hf, const float* __restrict__ hb,
                      const float* __restrict__ Wout, const float* __restrict__ bout,
                      float* __restrict__ out)
{
    int b = blockIdx.x, lane = threadIdx.x;
    const float4* hf4 = (const float4*)(hf + (size_t)b * HH);
    const float4* hb4 = (const float4*)(hb + (size_t)b * HH);
    const float4* wA  = (const float4*)Wout;
    const float4* wB  = (const float4*)(Wout + HH);
    float acc = 0.f;
#pragma unroll
    for (int i = 0; i < 2; ++i) {
        int idx = lane + 32*i;
        float4 a = hf4[idx], w = wA[idx];
        acc += a.x*w.x + a.y*w.y + a.z*w.z + a.w*w.w;
        float4 c = hb4[idx], v = wB[idx];
        acc += c.x*v.x + c.y*v.y + c.z*v.z + c.w*v.w;
    }
#pragma unroll
    for (int o = 16; o; o >>= 1) acc += __shfl_xor_sync(~0u, acc, o);
    if (lane == 0) out[b] = sigf(acc + bout[0]);
}

// ---------------- launch ----------------
extern "C" void kernel_launch(void* const* d_in, const int* in_sizes, int n_in,
                              void* d_out, int out_size)
{
    (void)in_sizes; (void)n_in; (void)out_size;
    const int*   seq  = (const int*)  d_in[0];
    const float* emb  = (const float*)d_in[1];
    const float* Wihf = (const float*)d_in[2];
    const float* Whhf = (const float*)d_in[3];
    const float* bf   = (const float*)d_in[4];
    const float* Wihb = (const float*)d_in[5];
    const float* Whhb = (const float*)d_in[6];
    const float* bb   = (const float*)d_in[7];
    const float* Wout = (const float*)d_in[8];
    const float* bout = (const float*)d_in[9];
    (void)Whhb;
    float* out = (float*)d_out;

    float *x, *xgf, *gb, *hf, *hb;
    cudaGetSymbolAddress((void**)&x,   g_x);
    cudaGetSymbolAddress((void**)&xgf, g_xg);
    cudaGetSymbolAddress((void**)&gb,  g_gb);
    cudaGetSymbolAddress((void**)&hf,  g_hf);
    cudaGetSymbolAddress((void**)&hb,  g_hb);

    const int SMEM_GEMM = 2 * 128 * 68 * 4;                  // 69632
    const int SMEM_SCAN = (16384*2 + 1088) * 4;              // 135424
    cudaFuncSetAttribute(k_gemm, cudaFuncAttributeMaxDynamicSharedMemorySize, SMEM_GEMM);
    cudaFuncSetAttribute(k_scan, cudaFuncAttributeMaxDynamicSharedMemorySize, SMEM_SCAN);

    k_embed<<<SQ*BB/4, 128>>>(seq, emb, x);
    dim3 g2(16, SQ*BB/64);
    k_gemm<<<g2, 256, SMEM_GEMM>>>(x, Wihf, bf, xgf);
    dim3 g2b(16, 1);
    k_gemm<<<g2b, 256, SMEM_GEMM>>>(x + (size_t)(SQ-1)*BB*EE, Wihb, bb, gb);
    k_scan<<<128, 256, SMEM_SCAN>>>(xgf, Whhf, hf);
    k_hback<<<64, 256>>>(gb, hb);
    k_out<<<64, 32>>>(hf, hb, Wout, bout, out);
}